// round 16
// baseline (speedup 1.0000x reference)
#include <cuda_runtime.h>
#include <cuda_fp16.h>

#define N_NODES 100000
#define N_EDGES 3200000
#define IN_F 128
#define HID 64
#define NC 16
#define NB ((N_NODES + 255) / 256)      // 391
#define FILL_BLKS (N_EDGES / 256)       // 12500 exact
#define GEMM_BLKS (N_NODES / 16)        // 6250 exact

// Scratch (static device globals — no allocation allowed)
__device__ __align__(16) float  g_dinv[N_NODES];
__device__ __align__(16) __half g_hs1h[N_NODES * HID];  // (x@W1)*dinv, fp16
__device__ __align__(16) __half g_hs2h[N_NODES * NC];   // (r1@W2)*dinv, fp16
__device__ int g_cnt[N_NODES];        // in-degree (edges only)
__device__ int g_cur[N_NODES];        // fill cursor (seeded with offsets)
__device__ int g_off[N_NODES];        // CSR offsets (by dst)
__device__ int g_ecsr[N_EDGES];       // src ids grouped by dst (compact, 12.8MB)
__device__ int g_total;
__device__ int g_is64;

// ---------------------------------------------------------------------------
// 0. fused: zero counters + detect int64 vs int32 (block 0 reads first 4096)
__global__ void k_prep(const long long* __restrict__ ei) {
    int i = blockIdx.x * 256 + threadIdx.x;
    if (i < N_NODES) g_cnt[i] = 0;
    if (blockIdx.x == 0) {
        __shared__ int bad;
        if (threadIdx.x == 0) { bad = 0; g_total = 0; }
        __syncthreads();
        for (int k = threadIdx.x; k < 4096; k += 256) {
            long long s = ei[k];
            if (s < 0 || s >= (long long)N_NODES) atomicOr(&bad, 1);
        }
        __syncthreads();
        if (threadIdx.x == 0) g_is64 = bad ? 0 : 1;
    }
}

// 1. degree count at dst
__global__ void k_deg(const void* __restrict__ ei) {
    int t = blockIdx.x * 256 + threadIdx.x;
    if (t >= N_EDGES) return;
    int dst;
    if (g_is64) dst = (int)((const long long*)ei)[N_EDGES + t];
    else        dst = ((const int*)ei)[N_EDGES + t];
    atomicAdd(&g_cnt[dst], 1);
}

// 2. scan-free CSR allocation: intra-block exclusive scan + one global atomic
//    per block for the base. Partition is run-order-dependent but always a
//    valid disjoint partition -> output unchanged (within atomic-order noise).
//    Also publishes dinv = rsqrt(deg+1).
__global__ void k_alloc() {
    __shared__ int s[256];
    __shared__ int boff;
    int t = threadIdx.x;
    int i = blockIdx.x * 256 + t;
    int c = (i < N_NODES) ? g_cnt[i] : 0;
    s[t] = c;
    __syncthreads();
    #pragma unroll
    for (int o = 1; o < 256; o <<= 1) {
        int v = (t >= o) ? s[t - o] : 0;
        __syncthreads();
        s[t] += v;
        __syncthreads();
    }
    if (t == 255) boff = atomicAdd(&g_total, s[255]);
    __syncthreads();
    if (i < N_NODES) {
        int off = boff + s[t] - c;
        g_off[i] = off;
        g_cur[i] = off;                 // absolute cursor for fill
        g_dinv[i] = rsqrtf((float)(c + 1));
    }
}

// 3. fused CSR-fill + GEMM1 (both depend only on alloc outputs).
//    blocks [0, FILL_BLKS): fill;  [FILL_BLKS, +GEMM_BLKS): gemm1.
__global__ __launch_bounds__(256) void k_fill_gemm1(const void* __restrict__ ei,
                                                    const float* __restrict__ x,
                                                    const float* __restrict__ W1) {
    __shared__ float Ws[IN_F * HID];      // 32 KB (gemm branch only)
    __shared__ float xs[16 * IN_F];       // 8 KB
    if (blockIdx.x < FILL_BLKS) {
        int t = blockIdx.x * 256 + threadIdx.x;   // exact
        int src, dst;
        if (g_is64) {
            const long long* p = (const long long*)ei;
            src = (int)p[t]; dst = (int)p[N_EDGES + t];
        } else {
            const int* p = (const int*)ei;
            src = p[t]; dst = p[N_EDGES + t];
        }
        g_ecsr[atomicAdd(&g_cur[dst], 1)] = src;
        return;
    }

    const int tid = threadIdx.x;
    const int tx = tid & 63;              // col 0..63
    const int ty = tid >> 6;              // row group 0..3
    const int base = (blockIdx.x - FILL_BLKS) * 16;

    #pragma unroll
    for (int i = tid; i < IN_F * HID; i += 256) Ws[i] = W1[i];
    #pragma unroll
    for (int i = tid; i < 16 * IN_F; i += 256) {
        int r = i >> 7, k = i & 127;
        xs[i] = x[(size_t)(base + r) * IN_F + k];
    }
    __syncthreads();

    float acc0 = 0.f, acc1 = 0.f, acc2 = 0.f, acc3 = 0.f;
    #pragma unroll
    for (int k4 = 0; k4 < IN_F; k4 += 4) {
        float4 x0 = *(const float4*)&xs[(ty * 4 + 0) * IN_F + k4];
        float4 x1 = *(const float4*)&xs[(ty * 4 + 1) * IN_F + k4];
        float4 x2 = *(const float4*)&xs[(ty * 4 + 2) * IN_F + k4];
        float4 x3 = *(const float4*)&xs[(ty * 4 + 3) * IN_F + k4];
        float w0 = Ws[(k4 + 0) * HID + tx];
        float w1 = Ws[(k4 + 1) * HID + tx];
        float w2 = Ws[(k4 + 2) * HID + tx];
        float w3 = Ws[(k4 + 3) * HID + tx];
        acc0 += x0.x * w0 + x0.y * w1 + x0.z * w2 + x0.w * w3;
        acc1 += x1.x * w0 + x1.y * w1 + x1.z * w2 + x1.w * w3;
        acc2 += x2.x * w0 + x2.y * w1 + x2.z * w2 + x2.w * w3;
        acc3 += x3.x * w0 + x3.y * w1 + x3.z * w2 + x3.w * w3;
    }
    float a[4] = {acc0, acc1, acc2, acc3};
    #pragma unroll
    for (int j = 0; j < 4; j++) {
        int row = base + ty * 4 + j;
        g_hs1h[(size_t)row * HID + tx] = __float2half(a[j] * g_dinv[row]);
    }
}

// 4. Layer-1 aggregation: 8-lane groups, uint4 (LDG.128) gathers, HADD2
//    accumulation flushed to fp32 every 8 edges; fused relu+bias+GEMM2.
//    32 nodes/block; lane owns features [lane*8, lane*8+8) = 4 half2.
__global__ __launch_bounds__(256) void k_agg1(const float* __restrict__ b1,
                                              const float* __restrict__ W2) {
    __shared__ float W2s[HID * NC];       // 4 KB
    __shared__ float r1s[32][65];         // padded, 8.3 KB
    const int t = threadIdx.x;
    const int g = t >> 3;
    const int lane = t & 7;
    #pragma unroll
    for (int i = t; i < HID * NC; i += 256) W2s[i] = W2[i];

    const int n = blockIdx.x * 32 + g;    // grid = 3125, exact
    const int start = g_off[n];
    const int end = start + g_cnt[n];
    const uint4* hv = (const uint4*)g_hs1h;   // 8 uint4 per row

    float a[8];
    {
        uint4 v = hv[(size_t)n * 8 + lane];   // self loop (fp32 unpack)
        float2 f0 = __half22float2(*reinterpret_cast<__half2*>(&v.x));
        float2 f1 = __half22float2(*reinterpret_cast<__half2*>(&v.y));
        float2 f2 = __half22float2(*reinterpret_cast<__half2*>(&v.z));
        float2 f3 = __half22float2(*reinterpret_cast<__half2*>(&v.w));
        a[0] = f0.x; a[1] = f0.y; a[2] = f1.x; a[3] = f1.y;
        a[4] = f2.x; a[5] = f2.y; a[6] = f3.x; a[7] = f3.y;
    }
    const unsigned m = 0xFFu << (t & 24);

    int j = start;
    for (; j + 8 <= end; j += 8) {
        int sv = g_ecsr[j + lane];
        __half2 p0 = __half2half2(__ushort_as_half(0));
        __half2 p1 = p0, p2 = p0, p3 = p0;
        #pragma unroll
        for (int q = 0; q < 8; q++) {
            int s = __shfl_sync(m, sv, q, 8);
            uint4 v = hv[(size_t)s * 8 + lane];
            p0 = __hadd2(p0, *reinterpret_cast<__half2*>(&v.x));
            p1 = __hadd2(p1, *reinterpret_cast<__half2*>(&v.y));
            p2 = __hadd2(p2, *reinterpret_cast<__half2*>(&v.z));
            p3 = __hadd2(p3, *reinterpret_cast<__half2*>(&v.w));
        }
        float2 f0 = __half22float2(p0), f1 = __half22float2(p1);
        float2 f2 = __half22float2(p2), f3 = __half22float2(p3);
        a[0] += f0.x; a[1] += f0.y; a[2] += f1.x; a[3] += f1.y;
        a[4] += f2.x; a[5] += f2.y; a[6] += f3.x; a[7] += f3.y;
    }
    int rem = end - j;
    if (rem > 0) {                        // <=7 edges, fp32 unpack path
        int sv = (lane < rem) ? g_ecsr[j + lane] : 0;
        for (int q = 0; q < rem; q++) {
            int s = __shfl_sync(m, sv, q, 8);
            uint4 v = hv[(size_t)s * 8 + lane];
            float2 f0 = __half22float2(*reinterpret_cast<__half2*>(&v.x));
            float2 f1 = __half22float2(*reinterpret_cast<__half2*>(&v.y));
            float2 f2 = __half22float2(*reinterpret_cast<__half2*>(&v.z));
            float2 f3 = __half22float2(*reinterpret_cast<__half2*>(&v.w));
            a[0] += f0.x; a[1] += f0.y; a[2] += f1.x; a[3] += f1.y;
            a[4] += f2.x; a[5] += f2.y; a[6] += f3.x; a[7] += f3.y;
        }
    }

    const float d = g_dinv[n];
    float4 bb0 = ((const float4*)b1)[lane * 2];
    float4 bb1 = ((const float4*)b1)[lane * 2 + 1];
    r1s[g][lane * 8 + 0] = fmaxf(a[0] * d + bb0.x, 0.f);
    r1s[g][lane * 8 + 1] = fmaxf(a[1] * d + bb0.y, 0.f);
    r1s[g][lane * 8 + 2] = fmaxf(a[2] * d + bb0.z, 0.f);
    r1s[g][lane * 8 + 3] = fmaxf(a[3] * d + bb0.w, 0.f);
    r1s[g][lane * 8 + 4] = fmaxf(a[4] * d + bb1.x, 0.f);
    r1s[g][lane * 8 + 5] = fmaxf(a[5] * d + bb1.y, 0.f);
    r1s[g][lane * 8 + 6] = fmaxf(a[6] * d + bb1.z, 0.f);
    r1s[g][lane * 8 + 7] = fmaxf(a[7] * d + bb1.w, 0.f);
    __syncthreads();

    // GEMM2: each lane computes 2 output cols (lane, lane+8)
    float o0 = 0.f, o1 = 0.f;
    #pragma unroll
    for (int k = 0; k < HID; k++) {
        float r = r1s[g][k];
        o0 += r * W2s[k * NC + lane];
        o1 += r * W2s[k * NC + lane + 8];
    }
    g_hs2h[(size_t)n * NC + lane]     = __float2half(o0 * d);
    g_hs2h[(size_t)n * NC + lane + 8] = __float2half(o1 * d);
}

// 5. Layer-2 aggregation (fp16 rows, HADD2, flush every 8) + final bias;
//    4-lane groups, lane owns 4 features = uint2; 64 nodes/block.
__global__ __launch_bounds__(256) void k_agg2(const float* __restrict__ b2,
                                              float* __restrict__ out) {
    const int t = threadIdx.x;
    const int g = t >> 2;
    const int lane = t & 3;
    const int n = blockIdx.x * 64 + g;
    if (n >= N_NODES) return;

    const int start = g_off[n];
    const int end = start + g_cnt[n];
    const uint2* hv = (const uint2*)g_hs2h;   // 4 uint2 per row

    float a0, a1, a2, a3;
    {
        uint2 v = hv[(size_t)n * 4 + lane];   // self loop
        float2 f0 = __half22float2(*reinterpret_cast<__half2*>(&v.x));
        float2 f1 = __half22float2(*reinterpret_cast<__half2*>(&v.y));
        a0 = f0.x; a1 = f0.y; a2 = f1.x; a3 = f1.y;
    }
    const unsigned qm = 0xFu << (t & 28);

    int j = start;
    for (; j + 8 <= end; j += 8) {
        __half2 p0 = __half2half2(__ushort_as_half(0));
        __half2 p1 = p0;
        #pragma unroll
        for (int h = 0; h < 2; h++) {
            int sv = g_ecsr[j + h * 4 + lane];
            #pragma unroll
            for (int q = 0; q < 4; q++) {
                int s = __shfl_sync(qm, sv, q, 4);
                uint2 v = hv[(size_t)s * 4 + lane];
                p0 = __hadd2(p0, *reinterpret_cast<__half2*>(&v.x));
                p1 = __hadd2(p1, *reinterpret_cast<__half2*>(&v.y));
            }
        }
        float2 f0 = __half22float2(p0), f1 = __half22float2(p1);
        a0 += f0.x; a1 += f0.y; a2 += f1.x; a3 += f1.y;
    }
    while (j < end) {                     // <=7 edges, fp32 unpack
        int b = end - j; if (b > 4) b = 4;
        int sv = (lane < b) ? g_ecsr[j + lane] : 0;
        for (int q = 0; q < b; q++) {
            int s = __shfl_sync(qm, sv, q, 4);
            uint2 v = hv[(size_t)s * 4 + lane];
            float2 f0 = __half22float2(*reinterpret_cast<__half2*>(&v.x));
            float2 f1 = __half22float2(*reinterpret_cast<__half2*>(&v.y));
            a0 += f0.x; a1 += f0.y; a2 += f1.x; a3 += f1.y;
        }
        j += b;
    }

    const float d = g_dinv[n];
    float4 bb = ((const float4*)b2)[lane];
    float4 r;
    r.x = a0 * d + bb.x;
    r.y = a1 * d + bb.y;
    r.z = a2 * d + bb.z;
    r.w = a3 * d + bb.w;
    ((float4*)out)[(size_t)n * 4 + lane] = r;
}

extern "C" void kernel_launch(void* const* d_in, const int* in_sizes, int n_in,
                              void* d_out, int out_size) {
    const float* x  = (const float*)d_in[0];
    const void*  ei = d_in[1];
    const float* W1 = (const float*)d_in[2];
    const float* b1 = (const float*)d_in[3];
    const float* W2 = (const float*)d_in[4];
    const float* b2 = (const float*)d_in[5];
    float* out = (float*)d_out;

    k_prep      <<<NB, 256>>>((const long long*)ei);          // idx 0
    k_deg       <<<(N_EDGES + 255) / 256, 256>>>(ei);         // idx 1
    k_alloc     <<<NB, 256>>>();                              // idx 2
    k_fill_gemm1<<<FILL_BLKS + GEMM_BLKS, 256>>>(ei, x, W1);  // idx 3  <- profiled
    k_agg1      <<<N_NODES / 32, 256>>>(b1, W2);              // idx 4
    k_agg2      <<<(N_NODES + 63) / 64, 256>>>(b2, out);      // idx 5
}

// round 17
// speedup vs baseline: 1.2918x; 1.2918x over previous
#include <cuda_runtime.h>
#include <cuda_fp16.h>

#define N_NODES 100000
#define N_EDGES 3200000
#define IN_F 128
#define HID 64
#define NC 16
#define NB ((N_NODES + 255) / 256)      // 391
#define GEMM_ROWS 32
#define GEMM_BLKS ((N_NODES + GEMM_ROWS - 1) / GEMM_ROWS)   // 3125 exact

// Scratch (static device globals — no allocation allowed)
__device__ __align__(16) float  g_dinv[N_NODES];
__device__ __align__(16) __half g_hs1h[N_NODES * HID];  // (x@W1)*dinv, fp16
__device__ __align__(16) __half g_hs2h[N_NODES * NC];   // (r1@W2)*dinv, fp16
__device__ int g_cnt[N_NODES];        // in-degree (edges only)
__device__ int g_cur[N_NODES];        // fill cursor (seeded with offsets)
__device__ int g_off[N_NODES];        // CSR offsets (by dst)
__device__ int g_ecsr[N_EDGES];       // src ids grouped by dst (compact, 12.8MB)
__device__ int g_total;
__device__ int g_is64;

// ---------------------------------------------------------------------------
// 0. fused: zero counters + detect int64 vs int32 (block 0 reads first 4096)
__global__ void k_prep(const long long* __restrict__ ei) {
    int i = blockIdx.x * 256 + threadIdx.x;
    if (i < N_NODES) g_cnt[i] = 0;
    if (blockIdx.x == 0) {
        __shared__ int bad;
        if (threadIdx.x == 0) { bad = 0; g_total = 0; }
        __syncthreads();
        for (int k = threadIdx.x; k < 4096; k += 256) {
            long long s = ei[k];
            if (s < 0 || s >= (long long)N_NODES) atomicOr(&bad, 1);
        }
        __syncthreads();
        if (threadIdx.x == 0) g_is64 = bad ? 0 : 1;
    }
}

// 1. degree count at dst
__global__ void k_deg(const void* __restrict__ ei) {
    int t = blockIdx.x * 256 + threadIdx.x;
    if (t >= N_EDGES) return;
    int dst;
    if (g_is64) dst = (int)((const long long*)ei)[N_EDGES + t];
    else        dst = ((const int*)ei)[N_EDGES + t];
    atomicAdd(&g_cnt[dst], 1);
}

// 2. scan-free CSR allocation: intra-block exclusive scan + one global atomic
//    per block for the base. Also publishes dinv = rsqrt(deg+1).
__global__ void k_alloc() {
    __shared__ int s[256];
    __shared__ int boff;
    int t = threadIdx.x;
    int i = blockIdx.x * 256 + t;
    int c = (i < N_NODES) ? g_cnt[i] : 0;
    s[t] = c;
    __syncthreads();
    #pragma unroll
    for (int o = 1; o < 256; o <<= 1) {
        int v = (t >= o) ? s[t - o] : 0;
        __syncthreads();
        s[t] += v;
        __syncthreads();
    }
    if (t == 255) boff = atomicAdd(&g_total, s[255]);
    __syncthreads();
    if (i < N_NODES) {
        int off = boff + s[t] - c;
        g_off[i] = off;
        g_cur[i] = off;                 // absolute cursor for fill
        g_dinv[i] = rsqrtf((float)(c + 1));
    }
}

// 3. GEMM1 v2: 32 rows x 64 cols per block, blockDim(32,8); each thread does
//    4 rows x 2 adjacent cols. x reads are warp-broadcast LDS.128; W reads are
//    conflict-free LDS.64. Epilogue writes __half2 per row.
__global__ __launch_bounds__(256) void k_gemm1(const float* __restrict__ x,
                                               const float* __restrict__ W1) {
    __shared__ float Ws[IN_F * HID];          // 32 KB, [k][c] row-major
    __shared__ float xs[GEMM_ROWS * IN_F];    // 16 KB
    const int tx = threadIdx.x;               // 0..31 -> cols 2tx, 2tx+1
    const int ty = threadIdx.y;               // 0..7  -> rows ty*4..ty*4+3
    const int tid = tx + 32 * ty;
    const int base = blockIdx.x * GEMM_ROWS;

    #pragma unroll
    for (int i = tid; i < IN_F * HID; i += 256) Ws[i] = W1[i];
    #pragma unroll
    for (int i = tid; i < GEMM_ROWS * IN_F; i += 256) {
        int r = i >> 7, k = i & 127;
        xs[i] = x[(size_t)(base + r) * IN_F + k];
    }
    __syncthreads();

    float a0[4] = {0.f, 0.f, 0.f, 0.f};   // col 2tx
    float a1[4] = {0.f, 0.f, 0.f, 0.f};   // col 2tx+1
    #pragma unroll
    for (int k4 = 0; k4 < IN_F; k4 += 4) {
        float2 w0 = *(const float2*)&Ws[(k4 + 0) * HID + 2 * tx];
        float2 w1 = *(const float2*)&Ws[(k4 + 1) * HID + 2 * tx];
        float2 w2 = *(const float2*)&Ws[(k4 + 2) * HID + 2 * tx];
        float2 w3 = *(const float2*)&Ws[(k4 + 3) * HID + 2 * tx];
        #pragma unroll
        for (int j = 0; j < 4; j++) {
            float4 xv = *(const float4*)&xs[(ty * 4 + j) * IN_F + k4];  // broadcast
            a0[j] += xv.x * w0.x + xv.y * w1.x + xv.z * w2.x + xv.w * w3.x;
            a1[j] += xv.x * w0.y + xv.y * w1.y + xv.z * w2.y + xv.w * w3.y;
        }
    }
    #pragma unroll
    for (int j = 0; j < 4; j++) {
        int row = base + ty * 4 + j;
        float d = g_dinv[row];
        __half2 h = __floats2half2_rn(a0[j] * d, a1[j] * d);
        *reinterpret_cast<__half2*>(&g_hs1h[(size_t)row * HID + 2 * tx]) = h;
    }
}

// 4. CSR fill (standalone, zero smem -> full occupancy)
__global__ void k_fill(const void* __restrict__ ei) {
    int t = blockIdx.x * 256 + threadIdx.x;   // grid exact
    int src, dst;
    if (g_is64) {
        const long long* p = (const long long*)ei;
        src = (int)p[t]; dst = (int)p[N_EDGES + t];
    } else {
        const int* p = (const int*)ei;
        src = p[t]; dst = p[N_EDGES + t];
    }
    g_ecsr[atomicAdd(&g_cur[dst], 1)] = src;
}

// 5. Layer-1 aggregation: 8-lane groups, uint4 (LDG.128) gathers, HADD2
//    accumulation flushed to fp32 every 8 edges; fused relu+bias+GEMM2.
//    32 nodes/block; lane owns features [lane*8, lane*8+8) = 4 half2.
__global__ __launch_bounds__(256) void k_agg1(const float* __restrict__ b1,
                                              const float* __restrict__ W2) {
    __shared__ float W2s[HID * NC];       // 4 KB
    __shared__ float r1s[32][65];         // padded, 8.3 KB
    const int t = threadIdx.x;
    const int g = t >> 3;
    const int lane = t & 7;
    #pragma unroll
    for (int i = t; i < HID * NC; i += 256) W2s[i] = W2[i];

    const int n = blockIdx.x * 32 + g;    // grid = 3125, exact
    const int start = g_off[n];
    const int end = start + g_cnt[n];
    const uint4* hv = (const uint4*)g_hs1h;   // 8 uint4 per row

    float a[8];
    {
        uint4 v = hv[(size_t)n * 8 + lane];   // self loop (fp32 unpack)
        float2 f0 = __half22float2(*reinterpret_cast<__half2*>(&v.x));
        float2 f1 = __half22float2(*reinterpret_cast<__half2*>(&v.y));
        float2 f2 = __half22float2(*reinterpret_cast<__half2*>(&v.z));
        float2 f3 = __half22float2(*reinterpret_cast<__half2*>(&v.w));
        a[0] = f0.x; a[1] = f0.y; a[2] = f1.x; a[3] = f1.y;
        a[4] = f2.x; a[5] = f2.y; a[6] = f3.x; a[7] = f3.y;
    }
    const unsigned m = 0xFFu << (t & 24);

    int j = start;
    for (; j + 8 <= end; j += 8) {
        int sv = g_ecsr[j + lane];
        __half2 p0 = __half2half2(__ushort_as_half(0));
        __half2 p1 = p0, p2 = p0, p3 = p0;
        #pragma unroll
        for (int q = 0; q < 8; q++) {
            int s = __shfl_sync(m, sv, q, 8);
            uint4 v = hv[(size_t)s * 8 + lane];
            p0 = __hadd2(p0, *reinterpret_cast<__half2*>(&v.x));
            p1 = __hadd2(p1, *reinterpret_cast<__half2*>(&v.y));
            p2 = __hadd2(p2, *reinterpret_cast<__half2*>(&v.z));
            p3 = __hadd2(p3, *reinterpret_cast<__half2*>(&v.w));
        }
        float2 f0 = __half22float2(p0), f1 = __half22float2(p1);
        float2 f2 = __half22float2(p2), f3 = __half22float2(p3);
        a[0] += f0.x; a[1] += f0.y; a[2] += f1.x; a[3] += f1.y;
        a[4] += f2.x; a[5] += f2.y; a[6] += f3.x; a[7] += f3.y;
    }
    int rem = end - j;
    if (rem > 0) {                        // <=7 edges, fp32 unpack path
        int sv = (lane < rem) ? g_ecsr[j + lane] : 0;
        for (int q = 0; q < rem; q++) {
            int s = __shfl_sync(m, sv, q, 8);
            uint4 v = hv[(size_t)s * 8 + lane];
            float2 f0 = __half22float2(*reinterpret_cast<__half2*>(&v.x));
            float2 f1 = __half22float2(*reinterpret_cast<__half2*>(&v.y));
            float2 f2 = __half22float2(*reinterpret_cast<__half2*>(&v.z));
            float2 f3 = __half22float2(*reinterpret_cast<__half2*>(&v.w));
            a[0] += f0.x; a[1] += f0.y; a[2] += f1.x; a[3] += f1.y;
            a[4] += f2.x; a[5] += f2.y; a[6] += f3.x; a[7] += f3.y;
        }
    }

    const float d = g_dinv[n];
    float4 bb0 = ((const float4*)b1)[lane * 2];
    float4 bb1 = ((const float4*)b1)[lane * 2 + 1];
    r1s[g][lane * 8 + 0] = fmaxf(a[0] * d + bb0.x, 0.f);
    r1s[g][lane * 8 + 1] = fmaxf(a[1] * d + bb0.y, 0.f);
    r1s[g][lane * 8 + 2] = fmaxf(a[2] * d + bb0.z, 0.f);
    r1s[g][lane * 8 + 3] = fmaxf(a[3] * d + bb0.w, 0.f);
    r1s[g][lane * 8 + 4] = fmaxf(a[4] * d + bb1.x, 0.f);
    r1s[g][lane * 8 + 5] = fmaxf(a[5] * d + bb1.y, 0.f);
    r1s[g][lane * 8 + 6] = fmaxf(a[6] * d + bb1.z, 0.f);
    r1s[g][lane * 8 + 7] = fmaxf(a[7] * d + bb1.w, 0.f);
    __syncthreads();

    // GEMM2: each lane computes 2 output cols (lane, lane+8)
    float o0 = 0.f, o1 = 0.f;
    #pragma unroll
    for (int k = 0; k < HID; k++) {
        float r = r1s[g][k];
        o0 += r * W2s[k * NC + lane];
        o1 += r * W2s[k * NC + lane + 8];
    }
    g_hs2h[(size_t)n * NC + lane]     = __float2half(o0 * d);
    g_hs2h[(size_t)n * NC + lane + 8] = __float2half(o1 * d);
}

// 6. Layer-2 aggregation (fp16 rows, HADD2, flush every 8) + final bias;
//    4-lane groups, lane owns 4 features = uint2; 64 nodes/block.
__global__ __launch_bounds__(256) void k_agg2(const float* __restrict__ b2,
                                              float* __restrict__ out) {
    const int t = threadIdx.x;
    const int g = t >> 2;
    const int lane = t & 3;
    const int n = blockIdx.x * 64 + g;
    if (n >= N_NODES) return;

    const int start = g_off[n];
    const int end = start + g_cnt[n];
    const uint2* hv = (const uint2*)g_hs2h;   // 4 uint2 per row

    float a0, a1, a2, a3;
    {
        uint2 v = hv[(size_t)n * 4 + lane];   // self loop
        float2 f0 = __half22float2(*reinterpret_cast<__half2*>(&v.x));
        float2 f1 = __half22float2(*reinterpret_cast<__half2*>(&v.y));
        a0 = f0.x; a1 = f0.y; a2 = f1.x; a3 = f1.y;
    }
    const unsigned qm = 0xFu << (t & 28);

    int j = start;
    for (; j + 8 <= end; j += 8) {
        __half2 p0 = __half2half2(__ushort_as_half(0));
        __half2 p1 = p0;
        #pragma unroll
        for (int h = 0; h < 2; h++) {
            int sv = g_ecsr[j + h * 4 + lane];
            #pragma unroll
            for (int q = 0; q < 4; q++) {
                int s = __shfl_sync(qm, sv, q, 4);
                uint2 v = hv[(size_t)s * 4 + lane];
                p0 = __hadd2(p0, *reinterpret_cast<__half2*>(&v.x));
                p1 = __hadd2(p1, *reinterpret_cast<__half2*>(&v.y));
            }
        }
        float2 f0 = __half22float2(p0), f1 = __half22float2(p1);
        a0 += f0.x; a1 += f0.y; a2 += f1.x; a3 += f1.y;
    }
    while (j < end) {                     // <=7 edges, fp32 unpack
        int b = end - j; if (b > 4) b = 4;
        int sv = (lane < b) ? g_ecsr[j + lane] : 0;
        for (int q = 0; q < b; q++) {
            int s = __shfl_sync(qm, sv, q, 4);
            uint2 v = hv[(size_t)s * 4 + lane];
            float2 f0 = __half22float2(*reinterpret_cast<__half2*>(&v.x));
            float2 f1 = __half22float2(*reinterpret_cast<__half2*>(&v.y));
            a0 += f0.x; a1 += f0.y; a2 += f1.x; a3 += f1.y;
        }
        j += b;
    }

    const float d = g_dinv[n];
    float4 bb = ((const float4*)b2)[lane];
    float4 r;
    r.x = a0 * d + bb.x;
    r.y = a1 * d + bb.y;
    r.z = a2 * d + bb.z;
    r.w = a3 * d + bb.w;
    ((float4*)out)[(size_t)n * 4 + lane] = r;
}

extern "C" void kernel_launch(void* const* d_in, const int* in_sizes, int n_in,
                              void* d_out, int out_size) {
    const float* x  = (const float*)d_in[0];
    const void*  ei = d_in[1];
    const float* W1 = (const float*)d_in[2];
    const float* b1 = (const float*)d_in[3];
    const float* W2 = (const float*)d_in[4];
    const float* b2 = (const float*)d_in[5];
    float* out = (float*)d_out;

    k_prep <<<NB, 256>>>((const long long*)ei);      // idx 0
    k_deg  <<<(N_EDGES + 255) / 256, 256>>>(ei);     // idx 1
    k_alloc<<<NB, 256>>>();                          // idx 2
    k_gemm1<<<GEMM_BLKS, dim3(32, 8)>>>(x, W1);      // idx 3  <- profiled slot
    k_fill <<<N_EDGES / 256, 256>>>(ei);             // idx 4
    k_agg1 <<<N_NODES / 32, 256>>>(b1, W2);          // idx 5
    k_agg2 <<<(N_NODES + 63) / 64, 256>>>(b2, out);  // idx 6
}